// round 2
// baseline (speedup 1.0000x reference)
#include <cuda_runtime.h>
#include <math.h>

// Problem constants (fixed by setup_inputs)
#define BS    8
#define HW    4096      // 64*64
#define VN    204       // hw // STEP
#define STEPV 20
#define PN    400
#define NT    128       // threads per block
#define SPLIT 2         // point-chunks per view (load balance)
#define CHUNK 200       // PN / SPLIT
#define NBLOCKS (VN * BS * SPLIT)

// Scratch accumulators (no cudaMalloc allowed). Zero-initialized at load;
// the last block resets them after use so every graph replay is identical.
__device__ double       g_acc[2];     // [0]=loss sum, [1]=value sum
__device__ unsigned int g_count = 0;

__global__ __launch_bounds__(NT) void loss_kernel(
    const float* __restrict__ pred_r,     // (bs,4,h,w)
    const float* __restrict__ pred_t,     // (bs,3,h,w)
    const float* __restrict__ pred_score, // (bs,h,w)
    const float* __restrict__ gt_r,       // (bs,3,3)
    const float* __restrict__ gt_t,       // (bs,3)
    const int*   __restrict__ cls_ids,    // (bs,)
    const float* __restrict__ model,      // (bs,3,P)
    float* __restrict__ out)
{
    const int v   = blockIdx.x;
    const int b   = blockIdx.y;
    const int z   = blockIdx.z;           // point-chunk id
    const int tid = threadIdx.x;
    const int p_base = z * CHUNK;

    const int c = cls_ids[b];
    const bool valid = (c >= 0 && c <= 29);   // (c+1) in SELECT_ID = 1..30
    const bool sym = (c == 12 || c == 15 || c == 18 || c == 19 || c == 20);

    __shared__ float4 smod[PN];   // (x,y,z,0)
    __shared__ float4 sgt[PN];    // (gx,gy,gz, gn = |g|^2)
    __shared__ float  red[NT / 32];

    float sum = 0.0f;

    if (valid) {
        // Stage model + gt = gt_r @ model + gt_t (tiny; sits in L2)
        {
            const float r00 = gt_r[b*9+0], r01 = gt_r[b*9+1], r02 = gt_r[b*9+2];
            const float r10 = gt_r[b*9+3], r11 = gt_r[b*9+4], r12 = gt_r[b*9+5];
            const float r20 = gt_r[b*9+6], r21 = gt_r[b*9+7], r22 = gt_r[b*9+8];
            const float t0  = gt_t[b*3+0], t1  = gt_t[b*3+1], t2  = gt_t[b*3+2];
            const float* mb = model + (size_t)b * 3 * PN;
            for (int p = tid; p < PN; p += NT) {
                const float x = mb[p], y = mb[PN + p], zz = mb[2*PN + p];
                smod[p] = make_float4(x, y, zz, 0.0f);
                const float gx = r00*x + r01*y + r02*zz + t0;
                const float gy = r10*x + r11*y + r12*zz + t1;
                const float gz = r20*x + r21*y + r22*zz + t2;
                sgt[p] = make_float4(gx, gy, gz, gx*gx + gy*gy + gz*gz);
            }
        }

        // Quaternion -> rotation (redundant per thread; cheap)
        const int pix = v * STEPV;
        const float* prb = pred_r + (size_t)b * 4 * HW;
        float q0 = prb[pix], q1 = prb[HW + pix], q2 = prb[2*HW + pix], q3 = prb[3*HW + pix];
        const float inv = rsqrtf(q0*q0 + q1*q1 + q2*q2 + q3*q3);
        q0 *= inv; q1 *= inv; q2 *= inv; q3 *= inv;

        const float R00 = 1.0f - 2.0f*(q2*q2 + q3*q3);
        const float R01 = 2.0f*q1*q2 - 2.0f*q0*q3;
        const float R02 = 2.0f*q0*q2 + 2.0f*q1*q3;
        const float R10 = 2.0f*q1*q2 + 2.0f*q3*q0;
        const float R11 = 1.0f - 2.0f*(q1*q1 + q3*q3);
        const float R12 = -2.0f*q0*q1 + 2.0f*q2*q3;
        const float R20 = -2.0f*q0*q2 + 2.0f*q1*q3;
        const float R21 = 2.0f*q0*q1 + 2.0f*q2*q3;
        const float R22 = 1.0f - 2.0f*(q1*q1 + q2*q2);

        const float* ptb = pred_t + (size_t)b * 3 * HW;
        const float tt0 = ptb[pix], tt1 = ptb[HW + pix], tt2 = ptb[2*HW + pix];

        __syncthreads();

        if (!sym) {
            // ADD: aligned per-point distance over this chunk
            #pragma unroll
            for (int k = 0; k < 2; k++) {
                const int pi = tid + k * NT;
                if (pi < CHUNK) {
                    const int p = p_base + pi;
                    const float4 m = smod[p];
                    const float4 g = sgt[p];
                    const float dx = R00*m.x + R01*m.y + R02*m.z + tt0 - g.x;
                    const float dy = R10*m.x + R11*m.y + R12*m.z + tt1 - g.y;
                    const float dz = R20*m.x + R21*m.y + R22*m.z + tt2 - g.z;
                    sum += sqrtf(dx*dx + dy*dy + dz*dz);
                }
            }
        } else {
            // ADD-S: d2 = pn + min_q( gn[q] - 2 p·g[q] ).  3 FFMA + 1 FMIN per pair.
            const bool act1 = (tid + NT) < CHUNK;
            const int p0 = p_base + tid;
            const int p1 = p_base + (act1 ? tid + NT : tid);

            float4 m0 = smod[p0], m1 = smod[p1];
            const float px0 = R00*m0.x + R01*m0.y + R02*m0.z + tt0;
            const float py0 = R10*m0.x + R11*m0.y + R12*m0.z + tt1;
            const float pz0 = R20*m0.x + R21*m0.y + R22*m0.z + tt2;
            const float px1 = R00*m1.x + R01*m1.y + R02*m1.z + tt0;
            const float py1 = R10*m1.x + R11*m1.y + R12*m1.z + tt1;
            const float pz1 = R20*m1.x + R21*m1.y + R22*m1.z + tt2;

            const float a0x = -2.0f*px0, a0y = -2.0f*py0, a0z = -2.0f*pz0;
            const float a1x = -2.0f*px1, a1y = -2.0f*py1, a1z = -2.0f*pz1;
            const float pn0 = px0*px0 + py0*py0 + pz0*pz0;
            const float pn1 = px1*px1 + py1*py1 + pz1*pz1;

            float min0 = 3.4e38f, min1 = 3.4e38f;
            #pragma unroll 4
            for (int q = 0; q < PN; q++) {
                const float4 g = sgt[q];            // one LDS.128, broadcast
                float t0 = fmaf(a0x, g.x, g.w);
                t0 = fmaf(a0y, g.y, t0);
                t0 = fmaf(a0z, g.z, t0);
                min0 = fminf(min0, t0);
                float t1 = fmaf(a1x, g.x, g.w);
                t1 = fmaf(a1y, g.y, t1);
                t1 = fmaf(a1z, g.z, t1);
                min1 = fminf(min1, t1);
            }
            sum = sqrtf(fmaxf(pn0 + min0, 0.0f));
            if (act1) sum += sqrtf(fmaxf(pn1 + min1, 0.0f));
        }
    }

    // Block reduction (uniform control flow)
    #pragma unroll
    for (int off = 16; off > 0; off >>= 1)
        sum += __shfl_down_sync(0xFFFFFFFFu, sum, off);
    if ((tid & 31) == 0) red[tid >> 5] = sum;
    __syncthreads();

    if (tid == 0) {
        if (valid) {
            float tot = red[0];
            #pragma unroll
            for (int w = 1; w < NT / 32; w++) tot += red[w];
            const float add_part = tot / (float)PN;   // partial of add_ij
            const int pix = v * STEPV;
            const float s = pred_score[(size_t)b * HW + pix];
            const double scale = 1.0 / ((double)VN * (double)BS);
            double lc = (double)(add_part * s);
            if (z == 0) lc += (double)(-0.01f * logf(s));  // log term once per view
            atomicAdd(&g_acc[0], lc * scale);
            atomicAdd(&g_acc[1], (double)add_part * scale);
        }
        __threadfence();
        const unsigned int old = atomicAdd(&g_count, 1u);
        if (old == (unsigned int)(NBLOCKS - 1)) {
            __threadfence();
            const double gl = *(volatile double*)&g_acc[0];
            const double gv = *(volatile double*)&g_acc[1];
            float glf = (float)gl;
            const float gvf = (float)gv;
            if (isinf(glf) || isnan(glf)) glf = 0.0f;
            out[0] = glf + 0.0f * gvf;   // faithful to reference
            // Reset for the next (graph-replayed) call — deterministic.
            g_acc[0] = 0.0;
            g_acc[1] = 0.0;
            g_count  = 0u;
        }
    }
}

extern "C" void kernel_launch(void* const* d_in, const int* in_sizes, int n_in,
                              void* d_out, int out_size) {
    const float* pred_r     = (const float*)d_in[0];
    const float* pred_t     = (const float*)d_in[1];
    const float* pred_score = (const float*)d_in[2];
    const float* gt_r       = (const float*)d_in[3];
    const float* gt_t       = (const float*)d_in[4];
    const int*   cls_ids    = (const int*)  d_in[5];
    const float* model_xyz  = (const float*)d_in[6];
    float* out = (float*)d_out;

    dim3 grid(VN, BS, SPLIT);
    loss_kernel<<<grid, NT>>>(pred_r, pred_t, pred_score, gt_r, gt_t,
                              cls_ids, model_xyz, out);
}

// round 3
// speedup vs baseline: 1.4975x; 1.4975x over previous
#include <cuda_runtime.h>
#include <math.h>
#include <stdint.h>

// Problem constants (fixed by setup_inputs)
#define BS    8
#define HW    4096      // 64*64
#define VN    204       // hw // STEP
#define STEPV 20
#define PN    400
#define NPAIR 200       // PN/2 packed gt pairs
#define NT    128       // threads per block
#define NBLOCKS (VN * BS)

// Scratch accumulators (no cudaMalloc allowed). Zero-initialized at load;
// last block resets them so every graph replay is identical.
__device__ double       g_acc[2];     // [0]=loss sum, [1]=value sum
__device__ unsigned int g_count = 0;

// Packed f32x2 FMA (Blackwell FFMA2 — only reachable via PTX)
#define FMA2(d, a, b, c) \
    asm("fma.rn.f32x2 %0, %1, %2, %3;" : "=l"(d) : "l"(a), "l"(b), "l"(c))
#define UNPACK2(lo, hi, v) \
    asm("mov.b64 {%0, %1}, %2;" : "=r"(lo), "=r"(hi) : "l"(v))

__device__ __forceinline__ uint64_t pack2(float lo, float hi) {
    return (uint64_t)__float_as_uint(lo) | ((uint64_t)__float_as_uint(hi) << 32);
}

__global__ __launch_bounds__(NT) void loss_kernel(
    const float* __restrict__ pred_r,     // (bs,4,h,w)
    const float* __restrict__ pred_t,     // (bs,3,h,w)
    const float* __restrict__ pred_score, // (bs,h,w)
    const float* __restrict__ gt_r,       // (bs,3,3)
    const float* __restrict__ gt_t,       // (bs,3)
    const int*   __restrict__ cls_ids,    // (bs,)
    const float* __restrict__ model,      // (bs,3,P)
    float* __restrict__ out)
{
    const int v   = blockIdx.x;
    const int b   = blockIdx.y;
    const int tid = threadIdx.x;

    const int c = cls_ids[b];
    const bool valid = (c >= 0 && c <= 29);   // (c+1) in SELECT_ID = 1..30
    const bool sym = (c == 12 || c == 15 || c == 18 || c == 19 || c == 20);

    // Packed gt staging (sym path only): sA[j] = {(x0,x1),(y0,y1)}, sB[j] = {(z0,z1),(w0,w1)}
    __shared__ ulonglong2 sA[NPAIR];
    __shared__ ulonglong2 sB[NPAIR];
    __shared__ float      red[NT / 32];

    float sum = 0.0f;

    if (valid) {
        // gt rotation/translation (broadcast loads, L2-resident)
        const float r00 = gt_r[b*9+0], r01 = gt_r[b*9+1], r02 = gt_r[b*9+2];
        const float r10 = gt_r[b*9+3], r11 = gt_r[b*9+4], r12 = gt_r[b*9+5];
        const float r20 = gt_r[b*9+6], r21 = gt_r[b*9+7], r22 = gt_r[b*9+8];
        const float t0  = gt_t[b*3+0], t1  = gt_t[b*3+1], t2  = gt_t[b*3+2];
        const float* mb = model + (size_t)b * 3 * PN;

        // Quaternion -> rotation for this view
        const int pix = v * STEPV;
        const float* prb = pred_r + (size_t)b * 4 * HW;
        float q0 = prb[pix], q1 = prb[HW + pix], q2 = prb[2*HW + pix], q3 = prb[3*HW + pix];
        const float inv = rsqrtf(q0*q0 + q1*q1 + q2*q2 + q3*q3);
        q0 *= inv; q1 *= inv; q2 *= inv; q3 *= inv;
        const float R00 = 1.0f - 2.0f*(q2*q2 + q3*q3);
        const float R01 = 2.0f*q1*q2 - 2.0f*q0*q3;
        const float R02 = 2.0f*q0*q2 + 2.0f*q1*q3;
        const float R10 = 2.0f*q1*q2 + 2.0f*q3*q0;
        const float R11 = 1.0f - 2.0f*(q1*q1 + q3*q3);
        const float R12 = -2.0f*q0*q1 + 2.0f*q2*q3;
        const float R20 = -2.0f*q0*q2 + 2.0f*q1*q3;
        const float R21 = 2.0f*q0*q1 + 2.0f*q2*q3;
        const float R22 = 1.0f - 2.0f*(q1*q1 + q2*q2);
        const float* ptb = pred_t + (size_t)b * 3 * HW;
        const float tt0 = ptb[pix], tt1 = ptb[HW + pix], tt2 = ptb[2*HW + pix];

        if (!sym) {
            // ADD path: no staging, no barrier. Each thread: up to 4 points.
            #pragma unroll
            for (int k = 0; k < 4; k++) {
                const int p = tid + k * NT;
                if (p < PN) {
                    const float x = mb[p], y = mb[PN + p], z = mb[2*PN + p];
                    const float dx = R00*x + R01*y + R02*z + tt0 - (r00*x + r01*y + r02*z + t0);
                    const float dy = R10*x + R11*y + R12*z + tt1 - (r10*x + r11*y + r12*z + t1);
                    const float dz = R20*x + R21*y + R22*z + tt2 - (r20*x + r21*y + r22*z + t2);
                    sum += sqrtf(dx*dx + dy*dy + dz*dz);
                }
            }
        } else {
            // Stage packed gt pairs: j covers points (2j, 2j+1)
            for (int j = tid; j < NPAIR; j += NT) {
                const float x0 = mb[2*j],     y0 = mb[PN + 2*j],     z0 = mb[2*PN + 2*j];
                const float x1 = mb[2*j + 1], y1 = mb[PN + 2*j + 1], z1 = mb[2*PN + 2*j + 1];
                const float gx0 = r00*x0 + r01*y0 + r02*z0 + t0;
                const float gy0 = r10*x0 + r11*y0 + r12*z0 + t1;
                const float gz0 = r20*x0 + r21*y0 + r22*z0 + t2;
                const float gx1 = r00*x1 + r01*y1 + r02*z1 + t0;
                const float gy1 = r10*x1 + r11*y1 + r12*z1 + t1;
                const float gz1 = r20*x1 + r21*y1 + r22*z1 + t2;
                const float gw0 = gx0*gx0 + gy0*gy0 + gz0*gz0;
                const float gw1 = gx1*gx1 + gy1*gy1 + gz1*gz1;
                sA[j] = make_ulonglong2(pack2(gx0, gx1), pack2(gy0, gy1));
                sB[j] = make_ulonglong2(pack2(gz0, gz1), pack2(gw0, gw1));
            }

            // Pred points: 4 per thread (pad duplicates tid's point, masked out)
            float pn_[4];
            uint64_t ax2[4], ay2[4], az2[4];
            bool act[4];
            #pragma unroll
            for (int k = 0; k < 4; k++) {
                const int p = tid + k * NT;
                act[k] = (p < PN);
                const int pp = act[k] ? p : tid;
                const float x = mb[pp], y = mb[PN + pp], z = mb[2*PN + pp];
                const float px = R00*x + R01*y + R02*z + tt0;
                const float py = R10*x + R11*y + R12*z + tt1;
                const float pz = R20*x + R21*y + R22*z + tt2;
                pn_[k] = px*px + py*py + pz*pz;
                ax2[k] = pack2(-2.0f*px, -2.0f*px);
                ay2[k] = pack2(-2.0f*py, -2.0f*py);
                az2[k] = pack2(-2.0f*pz, -2.0f*pz);
            }

            __syncthreads();

            float mind[4] = {3.4e38f, 3.4e38f, 3.4e38f, 3.4e38f};
            #pragma unroll 2
            for (int j = 0; j < NPAIR; j++) {
                const ulonglong2 A = sA[j];   // one LDS.128 (broadcast)
                const ulonglong2 B = sB[j];   // one LDS.128 (broadcast)
                #pragma unroll
                for (int k = 0; k < 4; k++) {
                    uint64_t t;
                    FMA2(t, az2[k], B.x, B.y);   // -2pz*gz + gn   (both halves)
                    FMA2(t, ay2[k], A.y, t);     // + -2py*gy
                    FMA2(t, ax2[k], A.x, t);     // + -2px*gx
                    uint32_t lo, hi;
                    UNPACK2(lo, hi, t);
                    mind[k] = fminf(mind[k], __uint_as_float(lo));
                    mind[k] = fminf(mind[k], __uint_as_float(hi));
                }
            }
            #pragma unroll
            for (int k = 0; k < 4; k++)
                if (act[k]) sum += sqrtf(fmaxf(pn_[k] + mind[k], 0.0f));
        }
    }

    // Block reduction (uniform control flow)
    #pragma unroll
    for (int off = 16; off > 0; off >>= 1)
        sum += __shfl_down_sync(0xFFFFFFFFu, sum, off);
    if ((tid & 31) == 0) red[tid >> 5] = sum;
    __syncthreads();

    if (tid == 0) {
        if (valid) {
            float tot = red[0];
            #pragma unroll
            for (int w = 1; w < NT / 32; w++) tot += red[w];
            const float add_ij = tot / (float)PN;
            const int pix = v * STEPV;
            const float s = pred_score[(size_t)b * HW + pix];
            const double scale = 1.0 / ((double)VN * (double)BS);
            atomicAdd(&g_acc[0], (double)(add_ij * s - 0.01f * logf(s)) * scale);
            atomicAdd(&g_acc[1], (double)add_ij * scale);
        }
        __threadfence();
        const unsigned int old = atomicAdd(&g_count, 1u);
        if (old == (unsigned int)(NBLOCKS - 1)) {
            __threadfence();
            const double gl = *(volatile double*)&g_acc[0];
            const double gv = *(volatile double*)&g_acc[1];
            float glf = (float)gl;
            const float gvf = (float)gv;
            if (isinf(glf) || isnan(glf)) glf = 0.0f;
            out[0] = glf + 0.0f * gvf;   // faithful to reference
            g_acc[0] = 0.0;
            g_acc[1] = 0.0;
            g_count  = 0u;
        }
    }
}

extern "C" void kernel_launch(void* const* d_in, const int* in_sizes, int n_in,
                              void* d_out, int out_size) {
    const float* pred_r     = (const float*)d_in[0];
    const float* pred_t     = (const float*)d_in[1];
    const float* pred_score = (const float*)d_in[2];
    const float* gt_r       = (const float*)d_in[3];
    const float* gt_t       = (const float*)d_in[4];
    const int*   cls_ids    = (const int*)  d_in[5];
    const float* model_xyz  = (const float*)d_in[6];
    float* out = (float*)d_out;

    dim3 grid(VN, BS);
    loss_kernel<<<grid, NT>>>(pred_r, pred_t, pred_score, gt_r, gt_t,
                              cls_ids, model_xyz, out);
}